// round 1
// baseline (speedup 1.0000x reference)
#include <cuda_runtime.h>
#include <cuda_bf16.h>

// LocallyConnected2d: out[b,o,y,x] = sum_{c,k} x[b,c,y+i,x+j] * w[o,c,y,x,k]
// B=16, C_IN=16, C_OUT=16, H=W=64, OH=OW=62, K=3x3.
//
// Strategy: per output position it's a 16x16x144 GEMM. Block covers one y row
// x 16 x-positions x all b x all o. Weight (35.4 MB, batch-invariant) is read
// exactly once, streamed coalesced ([x][k] are the contiguous inner dims).
// Compute uses packed fma.rn.f32x2 (o-pairs) for 2x fp32 throughput.

#define B_  16
#define CIN 16
#define CO  16
#define H_  64
#define W_  64
#define OH_ 62
#define OW_ 62
#define TX  16            // x-positions per block

// shared layouts (padded for conflict-free warp access)
#define SHX_BSTRIDE 60    // [b][r*18+cc], 4*60 = 240 ≡ 16 (mod 32) -> two 16-word runs land on disjoint bank halves
#define SHW_RSTRIDE 18    // [(xl*9+k)*18 + o], xl stride 162 ≡ 2 (mod 32) -> distinct even banks per xl

__device__ __forceinline__ void ffma2(unsigned long long& d,
                                      unsigned long long a,
                                      unsigned long long b) {
    asm("fma.rn.f32x2 %0, %1, %2, %0;" : "+l"(d) : "l"(a), "l"(b));
}

__device__ __forceinline__ unsigned long long bcast2(float v) {
    unsigned long long p;
    asm("mov.b64 %0, {%1, %1};" : "=l"(p) : "f"(v));
    return p;
}

__global__ __launch_bounds__(256)
void lc2d_kernel(const float* __restrict__ xin,
                 const float* __restrict__ wgt,
                 float* __restrict__ out) {
    __shared__ float sh_x[B_ * SHX_BSTRIDE];        // 960 floats
    __shared__ float sh_w[TX * 9 * SHW_RSTRIDE];    // 2592 floats

    const int tid  = threadIdx.x;
    const int xl   = tid & 15;     // x position within tile (fastest)
    const int slot = tid >> 4;     // 0..15
    const int sb   = slot & 3;     // batch group: b = sb*4 + bb
    const int ob   = slot >> 2;    // out-chan group: o = ob*4 + ...

    const int y  = blockIdx.y;
    const int x0 = blockIdx.x * TX;
    const int xt = min(TX, OW_ - x0);   // 16 or 14 (last tile)

    unsigned long long acc[4][2];
    #pragma unroll
    for (int bb = 0; bb < 4; ++bb) { acc[bb][0] = 0ull; acc[bb][1] = 0ull; }

    for (int c = 0; c < CIN; ++c) {
        __syncthreads();   // previous iteration's reads done

        // ---- stage weight tile: 16 o x (xt*9) contiguous floats each ----
        // global: w[((o*CIN + c)*OH + y)*OW + x0)*9 + r], r = xl*9 + k
        #pragma unroll
        for (int l = tid; l < CO * TX * 9; l += 256) {
            int o = l / (TX * 9);
            int r = l - o * (TX * 9);
            if (r < xt * 9) {
                sh_w[r * SHW_RSTRIDE + o] =
                    wgt[((((o * CIN + c) * OH_ + y) * OW_ + x0) * 9) + r];
            }
        }

        // ---- stage x patch: 16 b x 3 rows x 18 cols ----
        #pragma unroll
        for (int l = tid; l < B_ * 54; l += 256) {
            int b   = l / 54;
            int rem = l - b * 54;
            int r   = rem / 18;
            int cc  = rem - r * 18;
            int col = x0 + cc;
            float v = 0.0f;
            if (col < W_)
                v = xin[((b * CIN + c) * H_ + (y + r)) * W_ + col];
            sh_x[b * SHX_BSTRIDE + r * 18 + cc] = v;
        }

        __syncthreads();

        // ---- compute: 9 kernel taps ----
        #pragma unroll
        for (int k = 0; k < 9; ++k) {
            const int i = k / 3;
            const int j = k - i * 3;
            const float* wp = &sh_w[(xl * 9 + k) * SHW_RSTRIDE + ob * 4];
            unsigned long long wv0 = *reinterpret_cast<const unsigned long long*>(wp);
            unsigned long long wv1 = *reinterpret_cast<const unsigned long long*>(wp + 2);
            #pragma unroll
            for (int bb = 0; bb < 4; ++bb) {
                float xs = sh_x[(sb * 4 + bb) * SHX_BSTRIDE + i * 18 + xl + j];
                unsigned long long xp = bcast2(xs);
                ffma2(acc[bb][0], xp, wv0);
                ffma2(acc[bb][1], xp, wv1);
            }
        }
    }

    // ---- write outputs ----
    if (xl < xt) {
        #pragma unroll
        for (int bb = 0; bb < 4; ++bb) {
            const int b = sb * 4 + bb;
            #pragma unroll
            for (int p = 0; p < 2; ++p) {
                float lo, hi;
                asm("mov.b64 {%0, %1}, %2;" : "=f"(lo), "=f"(hi) : "l"(acc[bb][p]));
                const int o = ob * 4 + p * 2;
                out[((b * CO + o)     * OH_ + y) * OW_ + x0 + xl] = lo;
                out[((b * CO + o + 1) * OH_ + y) * OW_ + x0 + xl] = hi;
            }
        }
    }
}

extern "C" void kernel_launch(void* const* d_in, const int* in_sizes, int n_in,
                              void* d_out, int out_size) {
    const float* x = (const float*)d_in[0];
    const float* w = (const float*)d_in[1];
    float* out = (float*)d_out;
    dim3 grid((OW_ + TX - 1) / TX, OH_);   // (4, 62)
    lc2d_kernel<<<grid, 256>>>(x, w, out);
}

// round 2
// speedup vs baseline: 1.4904x; 1.4904x over previous
#include <cuda_runtime.h>
#include <cuda_bf16.h>
#include <cstdint>

// LocallyConnected2d: out[b,o,y,x] = sum_{c,k} x[b,c,y+i,x+j] * w[o,c,y,x,k]
// B=16, C_IN=16, C_OUT=16, H=W=64, OH=OW=62, K=3x3.
//
// R2: c-split 2 (grid z) for 2x blocks/SM + cp.async double-buffered staging
// to hide DRAM latency behind compute. Outputs combined via atomicAdd into a
// zero-initialized buffer (2 commutative contributions -> deterministic).

#define B_  16
#define CIN 16
#define CO  16
#define H_  64
#define W_  64
#define OH_ 62
#define OW_ 62
#define TX  16            // x-positions per block
#define NC  8             // channels per block (2-way c split)

#define WR  18            // weight smem row stride: [r = xl*9+k][o]
#define XS  60            // x smem batch stride: [b][r*18+cc]
#define WBUF (TX * 9 * WR)   // 2592 floats per buffer
#define XBUF (B_ * XS)       // 960 floats per buffer

#define WCSTRIDE (OH_ * OW_ * 9)  // weight float stride per c: 34596
#define XCSTRIDE (H_ * W_)        // x float stride per c: 4096

__device__ __forceinline__ void ffma2(unsigned long long& d,
                                      unsigned long long a,
                                      unsigned long long b) {
    asm("fma.rn.f32x2 %0, %1, %2, %0;" : "+l"(d) : "l"(a), "l"(b));
}

__device__ __forceinline__ unsigned long long bcast2(float v) {
    unsigned long long p;
    asm("mov.b64 %0, {%1, %1};" : "=l"(p) : "f"(v));
    return p;
}

__device__ __forceinline__ void cp_async4(uint32_t dst, const float* src, int sz) {
    asm volatile("cp.async.ca.shared.global [%0], [%1], 4, %2;\n"
                 :: "r"(dst), "l"(src), "r"(sz));
}

__global__ void zero_kernel(float* p, int n) {
    for (int i = blockIdx.x * blockDim.x + threadIdx.x; i < n;
         i += gridDim.x * blockDim.x)
        p[i] = 0.0f;
}

__global__ __launch_bounds__(256, 3)
void lc2d_kernel(const float* __restrict__ xin,
                 const float* __restrict__ wgt,
                 float* __restrict__ out) {
    __shared__ float sh_w[2 * WBUF];
    __shared__ float sh_x[2 * XBUF];

    const int tid  = threadIdx.x;
    const int xl   = tid & 15;     // x position within tile
    const int slot = tid >> 4;     // 0..15
    const int sb   = slot & 3;     // batch group
    const int ob   = slot >> 2;    // out-chan group

    const int y  = blockIdx.y;
    const int x0 = blockIdx.x * TX;
    const int xt = min(TX, OW_ - x0);   // 16 or 14
    const int xt9 = xt * 9;
    const int c0 = blockIdx.z * NC;

    const uint32_t shw_base = (uint32_t)__cvta_generic_to_shared(sh_w);
    const uint32_t shx_base = (uint32_t)__cvta_generic_to_shared(sh_x);

    // ---- staging descriptors (computed once) ----
    // weight: thread handles o = tid>>4, elements q = (tid&15) + 16n, n=0..8
    const int o_w = tid >> 4;
    const int qb  = tid & 15;
    const float* ws = wgt + ((((o_w * CIN + c0) * OH_ + y) * OW_ + x0) * 9) + qb;

    // x: thread handles b = tid>>4, elements rem = (tid&15) + 16n, n=0..3
    const int b_x = tid >> 4;
    const int jx  = tid & 15;
    int xoff[4], xsz[4];
    #pragma unroll
    for (int n = 0; n < 4; ++n) {
        int rem = jx + 16 * n;
        int r   = rem / 18;
        int cc  = rem - r * 18;
        bool ok = (rem < 54) && (x0 + cc < W_);
        xoff[n] = ok ? (r * W_ + cc) : 0;
        xsz[n]  = ok ? 4 : 0;
    }
    const float* xsb = xin + ((b_x * CIN + c0) * H_ + y) * W_ + x0;

    unsigned long long acc[4][2];
    #pragma unroll
    for (int bb = 0; bb < 4; ++bb) { acc[bb][0] = 0ull; acc[bb][1] = 0ull; }

    // ---- stage one channel's tiles into buffer `buf` ----
    auto stage = [&](int buf, const float* wsp, const float* xsp) {
        uint32_t wb = shw_base + buf * (WBUF * 4);
        #pragma unroll
        for (int n = 0; n < 9; ++n) {
            int q = qb + 16 * n;
            bool ok = q < xt9;
            cp_async4(wb + (uint32_t)(q * WR + o_w) * 4,
                      ok ? (wsp + 16 * n) : wgt, ok ? 4 : 0);
        }
        uint32_t xb = shx_base + buf * (XBUF * 4);
        #pragma unroll
        for (int n = 0; n < 4; ++n) {
            int rem = jx + 16 * n;
            if (rem < 54)
                cp_async4(xb + (uint32_t)(b_x * XS + rem) * 4,
                          xsp + xoff[n], xsz[n]);
        }
    };

    // prologue: stage c0
    stage(0, ws, xsb);
    asm volatile("cp.async.commit_group;\n" ::: "memory");

    #pragma unroll 1
    for (int ci = 0; ci < NC; ++ci) {
        if (ci + 1 < NC) {
            stage((ci + 1) & 1, ws + (ci + 1) * WCSTRIDE,
                  xsb + (ci + 1) * XCSTRIDE);
            asm volatile("cp.async.commit_group;\n" ::: "memory");
            asm volatile("cp.async.wait_group 1;\n" ::: "memory");
        } else {
            asm volatile("cp.async.wait_group 0;\n" ::: "memory");
        }
        __syncthreads();

        const float* swb = sh_w + (ci & 1) * WBUF;
        const float* sxb = sh_x + (ci & 1) * XBUF;

        #pragma unroll
        for (int k = 0; k < 9; ++k) {
            const int i = k / 3;
            const int j = k - i * 3;
            const float* wp = &swb[(xl * 9 + k) * WR + ob * 4];
            unsigned long long wv0 = *reinterpret_cast<const unsigned long long*>(wp);
            unsigned long long wv1 = *reinterpret_cast<const unsigned long long*>(wp + 2);
            #pragma unroll
            for (int bb = 0; bb < 4; ++bb) {
                float xs_v = sxb[(sb * 4 + bb) * XS + i * 18 + xl + j];
                unsigned long long xp = bcast2(xs_v);
                ffma2(acc[bb][0], xp, wv0);
                ffma2(acc[bb][1], xp, wv1);
            }
        }
        __syncthreads();
    }

    // ---- combine: exactly 2 contributions per output (c halves) ----
    if (xl < xt) {
        #pragma unroll
        for (int bb = 0; bb < 4; ++bb) {
            const int b = sb * 4 + bb;
            #pragma unroll
            for (int p = 0; p < 2; ++p) {
                float lo, hi;
                asm("mov.b64 {%0, %1}, %2;" : "=f"(lo), "=f"(hi) : "l"(acc[bb][p]));
                const int o = ob * 4 + p * 2;
                atomicAdd(&out[((b * CO + o)     * OH_ + y) * OW_ + x0 + xl], lo);
                atomicAdd(&out[((b * CO + o + 1) * OH_ + y) * OW_ + x0 + xl], hi);
            }
        }
    }
}

extern "C" void kernel_launch(void* const* d_in, const int* in_sizes, int n_in,
                              void* d_out, int out_size) {
    const float* x = (const float*)d_in[0];
    const float* w = (const float*)d_in[1];
    float* out = (float*)d_out;

    zero_kernel<<<240, 256>>>(out, out_size);

    dim3 grid((OW_ + TX - 1) / TX, OH_, 2);   // (4, 62, 2) = 496 blocks
    lc2d_kernel<<<grid, 256>>>(x, w, out);
}